// round 15
// baseline (speedup 1.0000x reference)
#include <cuda_runtime.h>
#include <cuda_bf16.h>
#include <cuda_fp16.h>

#define MAX_N 100000
#define MAX_E 1600000
#define IN_F 128
#define EDGE_F 16
#define SCAN_BLK 1024
#define MAX_SCAN_BLOCKS 128
#define N_PAD (MAX_N + 128)

// ---------------- static device scratch (allocation-free rule) --------------
__device__ __align__(16) int  g_cnt[MAX_N];
__device__ __align__(16) int  g_off[MAX_N];
__device__ __align__(16) int  g_cur[MAX_N];
__device__ __align__(16) int  g_bsum[MAX_SCAN_BLOCKS];
__device__ __align__(16) int  g_bbase[MAX_SCAN_BLOCKS];
__device__ __align__(16) int2 g_edges[MAX_E];
__device__ __align__(16) __half g_H2[(size_t)MAX_N * IN_F];          // fp16 copy of H
__device__ __align__(16) __nv_bfloat16 g_Ah[(size_t)N_PAD * IN_F];   // A hi
__device__ __align__(16) __nv_bfloat16 g_Al[(size_t)N_PAD * IN_F];   // A lo
__device__ __align__(16) __nv_bfloat16 g_W1h[IN_F * IN_F];  // [n][k] transposed
__device__ __align__(16) __nv_bfloat16 g_W1l[IN_F * IN_F];
__device__ __align__(16) __nv_bfloat16 g_W2h[IN_F * IN_F];
__device__ __align__(16) __nv_bfloat16 g_W2l[IN_F * IN_F];
__device__ int g_idx64;

// ------------------------------- helpers ------------------------------------
__device__ __forceinline__ unsigned cvt_bf16x2(float hi, float lo) {
    unsigned r; asm("cvt.rn.bf16x2.f32 %0, %1, %2;" : "=r"(r) : "f"(hi), "f"(lo));
    return r;
}
__device__ __forceinline__ float bflo_f(unsigned p) { return __uint_as_float(p << 16); }
__device__ __forceinline__ float bfhi_f(unsigned p) { return __uint_as_float(p & 0xffff0000u); }

__device__ __forceinline__ void mma16816(float c[4],
                                         unsigned a0, unsigned a1, unsigned a2, unsigned a3,
                                         unsigned b0, unsigned b1) {
    asm volatile(
        "mma.sync.aligned.m16n8k16.row.col.f32.bf16.bf16.f32 "
        "{%0,%1,%2,%3}, {%4,%5,%6,%7}, {%8,%9}, {%0,%1,%2,%3};"
        : "+f"(c[0]), "+f"(c[1]), "+f"(c[2]), "+f"(c[3])
        : "r"(a0), "r"(a1), "r"(a2), "r"(a3), "r"(b0), "r"(b1));
}

__device__ __forceinline__ int load_idx(const void* ei, size_t pos, int is64) {
    if (is64) return (int)(reinterpret_cast<const long long*>(ei)[pos]);
    return reinterpret_cast<const int*>(ei)[pos];
}

// ---------------------------------------------------------------------------
// 0) fused init: dtype detect + zero hist + W split/transpose + H -> fp16
__global__ void k_init(const int* __restrict__ ei_raw,
                       const float* __restrict__ W1, const float* __restrict__ W2,
                       const float* __restrict__ H, int N) {
    int i = blockIdx.x * blockDim.x + threadIdx.x;

    if (blockIdx.x == 0 && threadIdx.x < 32) {
        int lane = threadIdx.x;
        int nz = 0;
        for (int j = lane; j < 128; j += 32) nz |= ei_raw[2 * j + 1];
        unsigned b = __ballot_sync(0xffffffffu, nz != 0);
        if (lane == 0) g_idx64 = (b == 0) ? 1 : 0;
    }

    if (i < N) g_cnt[i] = 0;

    if (i < IN_F * IN_F) {          // i = k*128 + n
        int k = i >> 7, n = i & 127;
        float w = W1[i];
        __nv_bfloat16 h = __float2bfloat16(w);
        g_W1h[n * IN_F + k] = h;
        g_W1l[n * IN_F + k] = __float2bfloat16(w - __bfloat162float(h));
        w = W2[i];
        h = __float2bfloat16(w);
        g_W2h[n * IN_F + k] = h;
        g_W2l[n * IN_F + k] = __float2bfloat16(w - __bfloat162float(h));
    }

    // H -> fp16 (grid-stride over float2 pairs)
    size_t total2 = (size_t)N * IN_F / 2;
    size_t stride = (size_t)gridDim.x * blockDim.x;
    const float2* H2src = reinterpret_cast<const float2*>(H);
    __half2* H2dst = reinterpret_cast<__half2*>(g_H2);
    for (size_t j = i; j < total2; j += stride)
        H2dst[j] = __float22half2_rn(H2src[j]);
}

// ---------------------------------------------------------------------------
__global__ void k_hist(const void* __restrict__ ei, int E) {
    int e = blockIdx.x * blockDim.x + threadIdx.x;
    int is64 = g_idx64;
    if (e < E) {
        int dst = load_idx(ei, (size_t)E + e, is64);
        atomicAdd(&g_cnt[dst], 1);
    }
}

__global__ void k_scanA(int N) {
    __shared__ int s[SCAN_BLK];
    int t = threadIdx.x;
    int idx = blockIdx.x * SCAN_BLK + t;
    int v = (idx < N) ? g_cnt[idx] : 0;
    s[t] = v;
    __syncthreads();
    for (int off = 1; off < SCAN_BLK; off <<= 1) {
        int add = (t >= off) ? s[t - off] : 0;
        __syncthreads();
        s[t] += add;
        __syncthreads();
    }
    if (idx < N) g_off[idx] = s[t] - v;
    if (t == SCAN_BLK - 1) g_bsum[blockIdx.x] = s[t];
}

__global__ void k_scanB(int nb) {
    __shared__ int s[MAX_SCAN_BLOCKS];
    int t = threadIdx.x;
    int v = (t < nb) ? g_bsum[t] : 0;
    s[t] = v;
    __syncthreads();
    for (int off = 1; off < MAX_SCAN_BLOCKS; off <<= 1) {
        int add = (t >= off) ? s[t - off] : 0;
        __syncthreads();
        s[t] += add;
        __syncthreads();
    }
    if (t < nb) g_bbase[t] = s[t] - v;
}

__global__ void k_initcur(int N) {
    int i = blockIdx.x * blockDim.x + threadIdx.x;
    if (i < N) {
        int base = g_off[i] + g_bbase[i >> 10];
        g_off[i] = base;
        g_cur[i] = base;
    }
}

__global__ void k_scatter(const void* __restrict__ ei, int E) {
    int e = blockIdx.x * blockDim.x + threadIdx.x;
    int is64 = g_idx64;
    if (e < E) {
        int src = load_idx(ei, (size_t)e, is64);
        int dst = load_idx(ei, (size_t)E + e, is64);
        int p = atomicAdd(&g_cur[dst], 1);
        g_edges[p] = make_int2(src, e);
    }
}

// ---------------------------------------------------------------------------
// warp-per-node gather (H in fp16), 4-edge unrolled, split-bf16 A output
// ---------------------------------------------------------------------------
__global__ void __launch_bounds__(256)
k_gather(const float* __restrict__ EA,
         const float* __restrict__ We, const float* __restrict__ be, int N) {
    int warp = (int)((blockIdx.x * (size_t)blockDim.x + threadIdx.x) >> 5);
    int lane = threadIdx.x & 31;
    if (warp >= N) return;

    int start = g_off[warp];
    int d = g_cnt[warp];

    float4 accH = make_float4(0.f, 0.f, 0.f, 0.f);
    float eaSum = 0.f;   // lane k<16 holds sum of edge_attr[:,k]

    const int2* ep = g_edges + start;
    const uint2* H2 = reinterpret_cast<const uint2*>(g_H2);  // 4 fp16 per uint2

    int i = 0;
    for (; i + 4 <= d; i += 4) {
        int2 e0 = ep[i], e1 = ep[i + 1], e2 = ep[i + 2], e3 = ep[i + 3];
        uint2 u0 = H2[(size_t)e0.x * 32 + lane];
        uint2 u1 = H2[(size_t)e1.x * 32 + lane];
        uint2 u2 = H2[(size_t)e2.x * 32 + lane];
        uint2 u3 = H2[(size_t)e3.x * 32 + lane];
        float a0 = 0.f, a1 = 0.f, a2 = 0.f, a3 = 0.f;
        if (lane < EDGE_F) {
            a0 = EA[(size_t)e0.y * EDGE_F + lane];
            a1 = EA[(size_t)e1.y * EDGE_F + lane];
            a2 = EA[(size_t)e2.y * EDGE_F + lane];
            a3 = EA[(size_t)e3.y * EDGE_F + lane];
        }
        float2 f;
        f = __half22float2(*reinterpret_cast<__half2*>(&u0.x)); accH.x += f.x; accH.y += f.y;
        f = __half22float2(*reinterpret_cast<__half2*>(&u0.y)); accH.z += f.x; accH.w += f.y;
        f = __half22float2(*reinterpret_cast<__half2*>(&u1.x)); accH.x += f.x; accH.y += f.y;
        f = __half22float2(*reinterpret_cast<__half2*>(&u1.y)); accH.z += f.x; accH.w += f.y;
        f = __half22float2(*reinterpret_cast<__half2*>(&u2.x)); accH.x += f.x; accH.y += f.y;
        f = __half22float2(*reinterpret_cast<__half2*>(&u2.y)); accH.z += f.x; accH.w += f.y;
        f = __half22float2(*reinterpret_cast<__half2*>(&u3.x)); accH.x += f.x; accH.y += f.y;
        f = __half22float2(*reinterpret_cast<__half2*>(&u3.y)); accH.z += f.x; accH.w += f.y;
        eaSum += (a0 + a1) + (a2 + a3);
    }
    for (; i < d; i++) {
        int2 se = ep[i];
        uint2 u = H2[(size_t)se.x * 32 + lane];
        float2 f;
        f = __half22float2(*reinterpret_cast<__half2*>(&u.x)); accH.x += f.x; accH.y += f.y;
        f = __half22float2(*reinterpret_cast<__half2*>(&u.y)); accH.z += f.x; accH.w += f.y;
        if (lane < EDGE_F)
            eaSum += EA[(size_t)se.y * EDGE_F + lane];
    }

    float4 a = accH;
    #pragma unroll
    for (int k = 0; k < EDGE_F; k++) {
        float ek = __shfl_sync(0xffffffffu, eaSum, k);
        float4 w = reinterpret_cast<const float4*>(We + k * IN_F)[lane];
        a.x += ek * w.x; a.y += ek * w.y; a.z += ek * w.z; a.w += ek * w.w;
    }
    float degf = (float)d;
    float4 bv = reinterpret_cast<const float4*>(be)[lane];
    a.x += degf * bv.x; a.y += degf * bv.y; a.z += degf * bv.z; a.w += degf * bv.w;

    // split to bf16 hi/lo, store 8B each
    unsigned ph0 = cvt_bf16x2(a.y, a.x);
    unsigned ph1 = cvt_bf16x2(a.w, a.z);
    unsigned pl0 = cvt_bf16x2(a.y - bfhi_f(ph0), a.x - bflo_f(ph0));
    unsigned pl1 = cvt_bf16x2(a.w - bfhi_f(ph1), a.z - bflo_f(ph1));

    size_t base = (size_t)warp * IN_F + lane * 4;
    *reinterpret_cast<uint2*>(g_Ah + base) = make_uint2(ph0, ph1);
    *reinterpret_cast<uint2*>(g_Al + base) = make_uint2(pl0, pl1);
}

// ---------------------------------------------------------------------------
// Tensor-core MLP (R10 version): split-bf16 3-term mma.sync.
// Block = 64 rows / 4 warps. Warp owns 16 rows x 128 cols. Zero smem.
// ---------------------------------------------------------------------------
__global__ void __launch_bounds__(128)
k_mma(const float* __restrict__ b1, const float* __restrict__ b2,
      float* __restrict__ out, int N) {
    const int warp = threadIdx.x >> 5;
    const int lane = threadIdx.x & 31;
    const int g = lane >> 2;
    const int t = lane & 3;
    const int row0 = blockIdx.x * 64 + warp * 16;

    float c[16][4];

    // ---- GEMM1: C = A @ W1 + b1 ----
    #pragma unroll
    for (int nt = 0; nt < 16; nt++) {
        float v0 = b1[nt * 8 + 2 * t], v1 = b1[nt * 8 + 2 * t + 1];
        c[nt][0] = v0; c[nt][1] = v1; c[nt][2] = v0; c[nt][3] = v1;
    }

    {
        const size_t rA = (size_t)(row0 + g) * IN_F;
        const size_t rB = (size_t)(row0 + g + 8) * IN_F;
        #pragma unroll
        for (int ks = 0; ks < 8; ks++) {
            int col = ks * 16 + 2 * t;
            unsigned ah0 = *reinterpret_cast<const unsigned*>(g_Ah + rA + col);
            unsigned ah1 = *reinterpret_cast<const unsigned*>(g_Ah + rB + col);
            unsigned ah2 = *reinterpret_cast<const unsigned*>(g_Ah + rA + col + 8);
            unsigned ah3 = *reinterpret_cast<const unsigned*>(g_Ah + rB + col + 8);
            unsigned al0 = *reinterpret_cast<const unsigned*>(g_Al + rA + col);
            unsigned al1 = *reinterpret_cast<const unsigned*>(g_Al + rB + col);
            unsigned al2 = *reinterpret_cast<const unsigned*>(g_Al + rA + col + 8);
            unsigned al3 = *reinterpret_cast<const unsigned*>(g_Al + rB + col + 8);
            #pragma unroll
            for (int nt = 0; nt < 16; nt++) {
                int wb = (nt * 8 + g) * IN_F + ks * 16 + 2 * t;
                unsigned bh0 = *reinterpret_cast<const unsigned*>(g_W1h + wb);
                unsigned bh1 = *reinterpret_cast<const unsigned*>(g_W1h + wb + 8);
                unsigned bl0 = *reinterpret_cast<const unsigned*>(g_W1l + wb);
                unsigned bl1 = *reinterpret_cast<const unsigned*>(g_W1l + wb + 8);
                mma16816(c[nt], ah0, ah1, ah2, ah3, bh0, bh1);
                mma16816(c[nt], al0, al1, al2, al3, bh0, bh1);
                mma16816(c[nt], ah0, ah1, ah2, ah3, bl0, bl1);
            }
        }
    }

    // ---- relu + in-register split to GEMM2 A-fragments ----
    unsigned hh[16][2], hl[16][2];
    #pragma unroll
    for (int nt = 0; nt < 16; nt++) {
        float r0 = fmaxf(c[nt][0], 0.f), r1 = fmaxf(c[nt][1], 0.f);
        float r2 = fmaxf(c[nt][2], 0.f), r3 = fmaxf(c[nt][3], 0.f);
        unsigned p0 = cvt_bf16x2(r1, r0);
        unsigned p1 = cvt_bf16x2(r3, r2);
        hh[nt][0] = p0;
        hh[nt][1] = p1;
        hl[nt][0] = cvt_bf16x2(r1 - bfhi_f(p0), r0 - bflo_f(p0));
        hl[nt][1] = cvt_bf16x2(r3 - bfhi_f(p1), r2 - bflo_f(p1));
    }

    // ---- GEMM2: C = h @ W2 + b2 ----
    #pragma unroll
    for (int nt = 0; nt < 16; nt++) {
        float v0 = b2[nt * 8 + 2 * t], v1 = b2[nt * 8 + 2 * t + 1];
        c[nt][0] = v0; c[nt][1] = v1; c[nt][2] = v0; c[nt][3] = v1;
    }

    #pragma unroll
    for (int ks = 0; ks < 8; ks++) {
        unsigned ah0 = hh[2 * ks][0],     ah1 = hh[2 * ks][1];
        unsigned ah2 = hh[2 * ks + 1][0], ah3 = hh[2 * ks + 1][1];
        unsigned al0 = hl[2 * ks][0],     al1 = hl[2 * ks][1];
        unsigned al2 = hl[2 * ks + 1][0], al3 = hl[2 * ks + 1][1];
        #pragma unroll
        for (int nt = 0; nt < 16; nt++) {
            int wb = (nt * 8 + g) * IN_F + ks * 16 + 2 * t;
            unsigned bh0 = *reinterpret_cast<const unsigned*>(g_W2h + wb);
            unsigned bh1 = *reinterpret_cast<const unsigned*>(g_W2h + wb + 8);
            unsigned bl0 = *reinterpret_cast<const unsigned*>(g_W2l + wb);
            unsigned bl1 = *reinterpret_cast<const unsigned*>(g_W2l + wb + 8);
            mma16816(c[nt], ah0, ah1, ah2, ah3, bh0, bh1);
            mma16816(c[nt], al0, al1, al2, al3, bh0, bh1);
            mma16816(c[nt], ah0, ah1, ah2, ah3, bl0, bl1);
        }
    }

    // ---- epilogue ----
    int rowA = row0 + g, rowB = row0 + g + 8;
    #pragma unroll
    for (int nt = 0; nt < 16; nt++) {
        int colp = nt * 8 + 2 * t;
        if (rowA < N)
            *reinterpret_cast<float2*>(out + (size_t)rowA * IN_F + colp) =
                make_float2(c[nt][0], c[nt][1]);
        if (rowB < N)
            *reinterpret_cast<float2*>(out + (size_t)rowB * IN_F + colp) =
                make_float2(c[nt][2], c[nt][3]);
    }
}

// ---------------------------------------------------------------------------
extern "C" void kernel_launch(void* const* d_in, const int* in_sizes, int n_in,
                              void* d_out, int out_size) {
    const float* H  = (const float*)d_in[0];
    const void*  ei = d_in[1];
    const float* EA = (const float*)d_in[2];
    const float* We = (const float*)d_in[3];
    const float* be = (const float*)d_in[4];
    const float* W1 = (const float*)d_in[5];
    const float* b1 = (const float*)d_in[6];
    const float* W2 = (const float*)d_in[7];
    const float* b2 = (const float*)d_in[8];
    float* out = (float*)d_out;

    int N = in_sizes[0] / IN_F;
    int E = in_sizes[2] / EDGE_F;
    int nScanBlocks = (N + SCAN_BLK - 1) / SCAN_BLK;

    k_init<<<6250, 256>>>((const int*)ei, W1, W2, H, N);
    k_hist<<<(E + 255) / 256, 256>>>(ei, E);
    k_scanA<<<nScanBlocks, SCAN_BLK>>>(N);
    k_scanB<<<1, MAX_SCAN_BLOCKS>>>(nScanBlocks);
    k_initcur<<<(N + 255) / 256, 256>>>(N);
    k_scatter<<<(E + 255) / 256, 256>>>(ei, E);

    int gblocks = (N + 7) / 8;   // 8 warps (256 threads) per block
    k_gather<<<gblocks, 256>>>(EA, We, be, N);

    k_mma<<<(N + 63) / 64, 128>>>(b1, b2, out, N);
}

// round 17
// speedup vs baseline: 1.9683x; 1.9683x over previous
#include <cuda_runtime.h>
#include <cuda_fp16.h>

#define MAX_N 100000
#define MAX_E 1600000
#define IN_F 128
#define EDGE_F 16
#define SCAN_BLK 1024
#define MAX_SCAN_BLOCKS 128
#define N_PAD (MAX_N + 128)

// ---------------- static device scratch (allocation-free rule) --------------
__device__ __align__(16) int  g_cnt[MAX_N];
__device__ __align__(16) int  g_off[MAX_N];
__device__ __align__(16) int  g_cur[MAX_N];
__device__ __align__(16) int  g_bsum[MAX_SCAN_BLOCKS];
__device__ __align__(16) int  g_bbase[MAX_SCAN_BLOCKS];
__device__ __align__(16) int2 g_edges[MAX_E];
__device__ __align__(16) __half g_Af[(size_t)N_PAD * IN_F];   // A (fp16)
__device__ __align__(16) __half g_W1f[IN_F * IN_F];           // W1^T [n][k] fp16
__device__ __align__(16) __half g_W2f[IN_F * IN_F];           // W2^T [n][k] fp16
__device__ int g_idx64;

// ------------------------------- helpers ------------------------------------
__device__ __forceinline__ void mma16816_f16(float c[4],
                                             unsigned a0, unsigned a1, unsigned a2, unsigned a3,
                                             unsigned b0, unsigned b1) {
    asm volatile(
        "mma.sync.aligned.m16n8k16.row.col.f32.f16.f16.f32 "
        "{%0,%1,%2,%3}, {%4,%5,%6,%7}, {%8,%9}, {%0,%1,%2,%3};"
        : "+f"(c[0]), "+f"(c[1]), "+f"(c[2]), "+f"(c[3])
        : "r"(a0), "r"(a1), "r"(a2), "r"(a3), "r"(b0), "r"(b1));
}

__device__ __forceinline__ int load_idx(const void* ei, size_t pos, int is64) {
    if (is64) return (int)(reinterpret_cast<const long long*>(ei)[pos]);
    return reinterpret_cast<const int*>(ei)[pos];
}

__device__ __forceinline__ unsigned pack_h2(float lo, float hi) {
    __half2 h = __floats2half2_rn(lo, hi);
    return *reinterpret_cast<unsigned*>(&h);
}

// ---------------------------------------------------------------------------
// 0) fused init: dtype detect + zero hist + W transpose->fp16
__global__ void k_init(const int* __restrict__ ei_raw,
                       const float* __restrict__ W1, const float* __restrict__ W2,
                       int N) {
    int i = blockIdx.x * blockDim.x + threadIdx.x;

    if (blockIdx.x == 0 && threadIdx.x < 32) {
        int lane = threadIdx.x;
        int nz = 0;
        for (int j = lane; j < 128; j += 32) nz |= ei_raw[2 * j + 1];
        unsigned b = __ballot_sync(0xffffffffu, nz != 0);
        if (lane == 0) g_idx64 = (b == 0) ? 1 : 0;
    }

    if (i < N) g_cnt[i] = 0;

    if (i < IN_F * IN_F) {          // i = k*128 + n
        int k = i >> 7, n = i & 127;
        g_W1f[n * IN_F + k] = __float2half(W1[i]);
        g_W2f[n * IN_F + k] = __float2half(W2[i]);
    }
}

// ---------------------------------------------------------------------------
__global__ void k_hist(const void* __restrict__ ei, int E) {
    int e = blockIdx.x * blockDim.x + threadIdx.x;
    int is64 = g_idx64;
    if (e < E) {
        int dst = load_idx(ei, (size_t)E + e, is64);
        atomicAdd(&g_cnt[dst], 1);
    }
}

__global__ void k_scanA(int N) {
    __shared__ int s[SCAN_BLK];
    int t = threadIdx.x;
    int idx = blockIdx.x * SCAN_BLK + t;
    int v = (idx < N) ? g_cnt[idx] : 0;
    s[t] = v;
    __syncthreads();
    for (int off = 1; off < SCAN_BLK; off <<= 1) {
        int add = (t >= off) ? s[t - off] : 0;
        __syncthreads();
        s[t] += add;
        __syncthreads();
    }
    if (idx < N) g_off[idx] = s[t] - v;
    if (t == SCAN_BLK - 1) g_bsum[blockIdx.x] = s[t];
}

__global__ void k_scanB(int nb) {
    __shared__ int s[MAX_SCAN_BLOCKS];
    int t = threadIdx.x;
    int v = (t < nb) ? g_bsum[t] : 0;
    s[t] = v;
    __syncthreads();
    for (int off = 1; off < MAX_SCAN_BLOCKS; off <<= 1) {
        int add = (t >= off) ? s[t - off] : 0;
        __syncthreads();
        s[t] += add;
        __syncthreads();
    }
    if (t < nb) g_bbase[t] = s[t] - v;
}

__global__ void k_initcur(int N) {
    int i = blockIdx.x * blockDim.x + threadIdx.x;
    if (i < N) {
        int base = g_off[i] + g_bbase[i >> 10];
        g_off[i] = base;
        g_cur[i] = base;
    }
}

__global__ void k_scatter(const void* __restrict__ ei, int E) {
    int e = blockIdx.x * blockDim.x + threadIdx.x;
    int is64 = g_idx64;
    if (e < E) {
        int src = load_idx(ei, (size_t)e, is64);
        int dst = load_idx(ei, (size_t)E + e, is64);
        int p = atomicAdd(&g_cur[dst], 1);
        g_edges[p] = make_int2(src, e);
    }
}

// ---------------------------------------------------------------------------
// warp-per-node gather (f32 H, exactly the proven R10 path), fp16 A output
// ---------------------------------------------------------------------------
__global__ void __launch_bounds__(256)
k_gather(const float* __restrict__ H, const float* __restrict__ EA,
         const float* __restrict__ We, const float* __restrict__ be, int N) {
    int warp = (int)((blockIdx.x * (size_t)blockDim.x + threadIdx.x) >> 5);
    int lane = threadIdx.x & 31;
    if (warp >= N) return;

    int start = g_off[warp];
    int d = g_cnt[warp];

    float4 accH = make_float4(0.f, 0.f, 0.f, 0.f);
    float eaSum = 0.f;   // lane k<16 holds sum of edge_attr[:,k]

    const int2* ep = g_edges + start;
    const float4* H4 = reinterpret_cast<const float4*>(H);

    int i = 0;
    for (; i + 4 <= d; i += 4) {
        int2 e0 = ep[i], e1 = ep[i + 1], e2 = ep[i + 2], e3 = ep[i + 3];
        float4 h0 = H4[(size_t)e0.x * 32 + lane];
        float4 h1 = H4[(size_t)e1.x * 32 + lane];
        float4 h2 = H4[(size_t)e2.x * 32 + lane];
        float4 h3 = H4[(size_t)e3.x * 32 + lane];
        float a0 = 0.f, a1 = 0.f, a2 = 0.f, a3 = 0.f;
        if (lane < EDGE_F) {
            a0 = EA[(size_t)e0.y * EDGE_F + lane];
            a1 = EA[(size_t)e1.y * EDGE_F + lane];
            a2 = EA[(size_t)e2.y * EDGE_F + lane];
            a3 = EA[(size_t)e3.y * EDGE_F + lane];
        }
        accH.x += (h0.x + h1.x) + (h2.x + h3.x);
        accH.y += (h0.y + h1.y) + (h2.y + h3.y);
        accH.z += (h0.z + h1.z) + (h2.z + h3.z);
        accH.w += (h0.w + h1.w) + (h2.w + h3.w);
        eaSum += (a0 + a1) + (a2 + a3);
    }
    for (; i < d; i++) {
        int2 se = ep[i];
        float4 hv = H4[(size_t)se.x * 32 + lane];
        accH.x += hv.x; accH.y += hv.y; accH.z += hv.z; accH.w += hv.w;
        if (lane < EDGE_F)
            eaSum += EA[(size_t)se.y * EDGE_F + lane];
    }

    float4 a = accH;
    #pragma unroll
    for (int k = 0; k < EDGE_F; k++) {
        float ek = __shfl_sync(0xffffffffu, eaSum, k);
        float4 w = reinterpret_cast<const float4*>(We + k * IN_F)[lane];
        a.x += ek * w.x; a.y += ek * w.y; a.z += ek * w.z; a.w += ek * w.w;
    }
    float degf = (float)d;
    float4 bv = reinterpret_cast<const float4*>(be)[lane];
    a.x += degf * bv.x; a.y += degf * bv.y; a.z += degf * bv.z; a.w += degf * bv.w;

    // fp16 A row: lane holds cols 4l..4l+3 -> one 8B store
    unsigned p0 = pack_h2(a.x, a.y);
    unsigned p1 = pack_h2(a.z, a.w);
    *reinterpret_cast<uint2*>(g_Af + (size_t)warp * IN_F + lane * 4) =
        make_uint2(p0, p1);
}

// ---------------------------------------------------------------------------
// Tensor-core MLP, single fp16 mma.sync (f32 accum). 256 HMMA/warp.
// Block = 64 rows / 4 warps. Warp owns 16 rows x 128 cols. Zero smem.
// ---------------------------------------------------------------------------
__global__ void __launch_bounds__(128)
k_mma(const float* __restrict__ b1, const float* __restrict__ b2,
      float* __restrict__ out, int N) {
    const int warp = threadIdx.x >> 5;
    const int lane = threadIdx.x & 31;
    const int g = lane >> 2;
    const int t = lane & 3;
    const int row0 = blockIdx.x * 64 + warp * 16;
    const int rowA = row0 + g, rowB = row0 + g + 8;

    float c[16][4];

    // ---- GEMM1: C = A @ W1 + b1 ----
    #pragma unroll
    for (int nt = 0; nt < 16; nt++) {
        float v0 = b1[nt * 8 + 2 * t], v1 = b1[nt * 8 + 2 * t + 1];
        c[nt][0] = v0; c[nt][1] = v1; c[nt][2] = v0; c[nt][3] = v1;
    }

    {
        const size_t rA = (size_t)rowA * IN_F;
        const size_t rB = (size_t)rowB * IN_F;
        #pragma unroll
        for (int ks = 0; ks < 8; ks++) {
            int col = ks * 16 + 2 * t;
            unsigned a0 = *reinterpret_cast<const unsigned*>(g_Af + rA + col);
            unsigned a1 = *reinterpret_cast<const unsigned*>(g_Af + rB + col);
            unsigned a2 = *reinterpret_cast<const unsigned*>(g_Af + rA + col + 8);
            unsigned a3 = *reinterpret_cast<const unsigned*>(g_Af + rB + col + 8);
            #pragma unroll
            for (int nt = 0; nt < 16; nt++) {
                int wb = (nt * 8 + g) * IN_F + ks * 16 + 2 * t;
                unsigned b0 = *reinterpret_cast<const unsigned*>(g_W1f + wb);
                unsigned b1v = *reinterpret_cast<const unsigned*>(g_W1f + wb + 8);
                mma16816_f16(c[nt], a0, a1, a2, a3, b0, b1v);
            }
        }
    }

    // ---- relu -> fp16 A-fragments for GEMM2 ----
    unsigned hh[16][2];
    #pragma unroll
    for (int nt = 0; nt < 16; nt++) {
        hh[nt][0] = pack_h2(fmaxf(c[nt][0], 0.f), fmaxf(c[nt][1], 0.f));
        hh[nt][1] = pack_h2(fmaxf(c[nt][2], 0.f), fmaxf(c[nt][3], 0.f));
    }

    // ---- GEMM2: C = h @ W2 + b2 ----
    #pragma unroll
    for (int nt = 0; nt < 16; nt++) {
        float v0 = b2[nt * 8 + 2 * t], v1 = b2[nt * 8 + 2 * t + 1];
        c[nt][0] = v0; c[nt][1] = v1; c[nt][2] = v0; c[nt][3] = v1;
    }

    #pragma unroll
    for (int ks = 0; ks < 8; ks++) {
        unsigned a0 = hh[2 * ks][0],     a1 = hh[2 * ks][1];
        unsigned a2 = hh[2 * ks + 1][0], a3 = hh[2 * ks + 1][1];
        #pragma unroll
        for (int nt = 0; nt < 16; nt++) {
            int wb = (nt * 8 + g) * IN_F + ks * 16 + 2 * t;
            unsigned b0 = *reinterpret_cast<const unsigned*>(g_W2f + wb);
            unsigned b1v = *reinterpret_cast<const unsigned*>(g_W2f + wb + 8);
            mma16816_f16(c[nt], a0, a1, a2, a3, b0, b1v);
        }
    }

    // ---- epilogue ----
    #pragma unroll
    for (int nt = 0; nt < 16; nt++) {
        int colp = nt * 8 + 2 * t;
        if (rowA < N)
            *reinterpret_cast<float2*>(out + (size_t)rowA * IN_F + colp) =
                make_float2(c[nt][0], c[nt][1]);
        if (rowB < N)
            *reinterpret_cast<float2*>(out + (size_t)rowB * IN_F + colp) =
                make_float2(c[nt][2], c[nt][3]);
    }
}

// ---------------------------------------------------------------------------
extern "C" void kernel_launch(void* const* d_in, const int* in_sizes, int n_in,
                              void* d_out, int out_size) {
    const float* H  = (const float*)d_in[0];
    const void*  ei = d_in[1];
    const float* EA = (const float*)d_in[2];
    const float* We = (const float*)d_in[3];
    const float* be = (const float*)d_in[4];
    const float* W1 = (const float*)d_in[5];
    const float* b1 = (const float*)d_in[6];
    const float* W2 = (const float*)d_in[7];
    const float* b2 = (const float*)d_in[8];
    float* out = (float*)d_out;

    int N = in_sizes[0] / IN_F;
    int E = in_sizes[2] / EDGE_F;
    int nScanBlocks = (N + SCAN_BLK - 1) / SCAN_BLK;
    int initBlocks = ((N > IN_F * IN_F ? N : IN_F * IN_F) + 255) / 256;

    k_init<<<initBlocks, 256>>>((const int*)ei, W1, W2, N);
    k_hist<<<(E + 255) / 256, 256>>>(ei, E);
    k_scanA<<<nScanBlocks, SCAN_BLK>>>(N);
    k_scanB<<<1, MAX_SCAN_BLOCKS>>>(nScanBlocks);
    k_initcur<<<(N + 255) / 256, 256>>>(N);
    k_scatter<<<(E + 255) / 256, 256>>>(ei, E);

    int gblocks = (N + 7) / 8;   // 8 warps (256 threads) per block
    k_gather<<<gblocks, 256>>>(H, EA, We, be, N);

    k_mma<<<(N + 63) / 64, 128>>>(b1, b2, out, N);
}